// round 11
// baseline (speedup 1.0000x reference)
#include <cuda_runtime.h>
#include <cuda.h>
#include <cstdint>

#define BSZ 4096
#define DIM 1024
#define NST 2900000
#define NCOPY 512
#define NCHUNK ((BSZ * DIM) / 16)

// tc-path tiling
#define MT 128
#define NTL 256
#define NBX 16
#define NBY 32
#define NCPB 128
#define NSTAGE 64          // K-chunks of 16

#define GAMMA_S 0.8f
#define GAMMA_U 0.8f
#define RHO 0.1f
#define EPS_ 1e-10f
#define TAU_MIN_ 0.005f
#define TAU_MAX_ 1.0f
#define GRAD_CLIP_ 5.0f
#define ETA_INIT_ 0.01f
#define ETA_MIN_ 0.0001f

#define OG_I   0
#define OG_T   (BSZ)
#define OGR_I  (2*BSZ)
#define OGR_T  (3*BSZ)
#define O_LOSS (4*BSZ)
#define O_AVGI (4*BSZ+1)
#define O_AVGT (4*BSZ+2)
#define O_STATE (4*BSZ+3)
#define O_SI   (O_STATE + 0*NST)
#define O_ST   (O_STATE + 1*NST)
#define O_UI   (O_STATE + 2*NST)
#define O_UT   (O_STATE + 3*NST)
#define O_BI   (O_STATE + 4*NST)
#define O_BT   (O_STATE + 5*NST)
#define O_TAUI (O_STATE + 6*NST)
#define O_TAUT (O_STATE + 7*NST)

// ---- arch-specific feature gate ----
#if defined(__CUDA_ARCH_FEAT_SM103_ALL) || defined(__CUDA_ARCH_FEAT_SM100_ALL) || defined(__CUDA_ARCH_FEAT_SM101_ALL)
#define HAS_TC 1
#else
#define HAS_TC 0
#endif

__device__ int g_use_tc = HAS_TC;

// ----- shared scratch -----
__device__ uint32_t g_A32[(size_t)BSZ * DIM];
__device__ uint32_t g_B32[(size_t)BSZ * DIM];
__device__ float g_rowM[BSZ * 32], g_rowS[BSZ * 32], g_rowW[BSZ * 32];
__device__ float g_colM[BSZ * 32], g_colS[BSZ * 32], g_colW[BSZ * 32];
__device__ float g_diag[BSZ];
__device__ float g_loss_img[BSZ], g_loss_txt[BSZ];
__device__ float g_tau_img[BSZ], g_tau_txt[BSZ];

// ===================== common helpers =====================

__device__ __forceinline__ uint32_t f2tf32(float x) {
    uint32_t r; asm("cvt.rna.tf32.f32 %0, %1;" : "=r"(r) : "f"(x)); return r;
}
__device__ __forceinline__ float eta_of(int ep, int mep) {
    float r = (float)ep / (float)mep;
    return ETA_MIN_ + (ETA_INIT_ - ETA_MIN_) * cosf(1.5707963267948966f * r);
}
__device__ __forceinline__ void omerge(float& m, float& S, float& W,
                                       float om, float oS, float oW) {
    float mn = fmaxf(m, om);
    float ea = __expf(m - mn), eb = __expf(om - mn);
    S = S * ea + oS * eb;
    W = W * ea + oW * eb;
    m = mn;
}
__device__ __forceinline__ uint32_t smem_u32(const void* p) {
    uint32_t a;
    asm("{ .reg .u64 t; cvta.to.shared.u64 t, %1; cvt.u32.u64 %0, t; }" : "=r"(a) : "l"(p));
    return a;
}

// =====================================================================
// ======================  TC PATH (sm_103a only)  =====================
// =====================================================================

// smem map: K-chunk 16 (64B rows, SW64), 2-stage ring
#define SM_TMEM   0
#define SM_FULL(s)  (8 + (s) * 8)
#define SM_EMPTY(s) (24 + (s) * 8)
#define SM_DONE   40
#define SM_ITT    256        // 256 f32
#define SM_ITR    1280       // 128 f32
#define SM_PM     1792
#define SM_PS     2304
#define SM_PW     2816
#define SM_A(s)   (4096 + (s) * 8192)     // 2 x 8 KB
#define SM_B(s)   (20480 + (s) * 16384)   // 2 x 16 KB
#define SM_T      4096                     // epilogue reuse of stage region
#define SMEM_TC   90112                    // padded: forces exactly 2 CTAs/SM
#define STAGE_BYTES (8192 + 16384)

#define IDESC_TF32 0x8400910u   // kind::tf32, F32 acc, M=128, N=256

#if HAS_TC
#define MBAR_INIT(a, c) \
    asm volatile("mbarrier.init.shared.b64 [%0], %1;" :: "r"(a), "r"(c) : "memory")
#define MBAR_EXPECT_TX(a, b) \
    asm volatile("mbarrier.arrive.expect_tx.shared.b64 _, [%0], %1;" :: "r"(a), "r"(b) : "memory")
#define TMA2D(sm, tmap, cx, cy, mb) \
    asm volatile("cp.async.bulk.tensor.2d.shared::cta.global.tile.mbarrier::complete_tx::bytes " \
                 "[%0], [%1, {%2, %3}], [%4];" \
                 :: "r"(sm), "l"(tmap), "r"(cx), "r"(cy), "r"(mb) : "memory")
#define TCG_ALLOC(d, n) \
    asm volatile("tcgen05.alloc.cta_group::1.sync.aligned.shared::cta.b32 [%0], %1;" :: "r"(d), "r"(n) : "memory")
#define TCG_DEALLOC(a, n) \
    asm volatile("tcgen05.dealloc.cta_group::1.sync.aligned.b32 %0, %1;" :: "r"(a), "r"(n))
#define TCG_RELINQ() asm volatile("tcgen05.relinquish_alloc_permit.cta_group::1.sync.aligned;")
#define TCG_COMMIT(mb) \
    asm volatile("tcgen05.commit.cta_group::1.mbarrier::arrive::one.shared::cluster.b64 [%0];" :: "r"(mb) : "memory")
#define TCG_WAIT_LD() asm volatile("tcgen05.wait::ld.sync.aligned;" ::: "memory")
#define TCG_FENCE_AFTER() asm volatile("tcgen05.fence::after_thread_sync;" ::: "memory")

__device__ __forceinline__ void mbar_wait(uint32_t mbar, uint32_t par) {
    asm volatile(
        "{\n\t.reg .pred P;\n\tW_%=:\n\t"
        "mbarrier.try_wait.parity.acquire.cta.shared::cta.b64 P, [%0], %1, 0x989680;\n\t"
        "@!P bra W_%=;\n\t}" :: "r"(mbar), "r"(par) : "memory");
}
__device__ __forceinline__ void mma_tf32_ss(uint32_t d, uint64_t ad, uint64_t bd, uint32_t en) {
    asm volatile(
        "{\n\t.reg .pred p;\n\tsetp.ne.u32 p, %4, 0;\n\t"
        "tcgen05.mma.cta_group::1.kind::tf32 [%0], %1, %2, %3, {%5,%5,%5,%5}, p;\n\t}"
        :: "r"(d), "l"(ad), "l"(bd), "r"(IDESC_TF32), "r"(en), "r"(0u) : "memory");
}
#define LDTM_X32(r, addr) \
    asm volatile("tcgen05.ld.sync.aligned.32x32b.x32.b32 " \
        "{%0,%1,%2,%3,%4,%5,%6,%7,%8,%9,%10,%11,%12,%13,%14,%15," \
        "%16,%17,%18,%19,%20,%21,%22,%23,%24,%25,%26,%27,%28,%29,%30,%31}, [%32];" \
        : "=r"((r)[0]),"=r"((r)[1]),"=r"((r)[2]),"=r"((r)[3]),"=r"((r)[4]),"=r"((r)[5]), \
          "=r"((r)[6]),"=r"((r)[7]),"=r"((r)[8]),"=r"((r)[9]),"=r"((r)[10]),"=r"((r)[11]), \
          "=r"((r)[12]),"=r"((r)[13]),"=r"((r)[14]),"=r"((r)[15]),"=r"((r)[16]),"=r"((r)[17]), \
          "=r"((r)[18]),"=r"((r)[19]),"=r"((r)[20]),"=r"((r)[21]),"=r"((r)[22]),"=r"((r)[23]), \
          "=r"((r)[24]),"=r"((r)[25]),"=r"((r)[26]),"=r"((r)[27]),"=r"((r)[28]),"=r"((r)[29]), \
          "=r"((r)[30]),"=r"((r)[31]) : "r"(addr))

// SW64 K-major descriptor: layout=4, version=1, SBO=32 (512B per 8-row group), LBO=1
static __device__ __forceinline__ uint64_t smem_desc_sw64(uint32_t addr) {
    return ((uint64_t)4 << 61) | ((uint64_t)1 << 46) | ((uint64_t)32 << 32) |
           ((uint64_t)1 << 16) | (uint64_t)((addr >> 4) & 0x3FFF);
}
#endif  // HAS_TC

// ---- tc convert: RNA-round fp32 -> tf32 bits ----
__global__ void __launch_bounds__(256) convert_tf32(
    const float* __restrict__ A, const float* __restrict__ Bm)
{
    size_t t = (size_t)blockIdx.x * 256 + threadIdx.x;
    const float* src = A; uint32_t* dst = g_A32;
    if (t >= (1u << 20)) { t -= (1u << 20); src = Bm; dst = g_B32; }
    float4 v = ((const float4*)src)[t];
    ((uint4*)dst)[t] = make_uint4(f2tf32(v.x), f2tf32(v.y), f2tf32(v.z), f2tf32(v.w));
}

// ---- tc GEMM + fused partials + state copy (2 CTAs/SM) ----
__global__ void __launch_bounds__(128) gemm_tc(
    const __grid_constant__ CUtensorMap tmA,
    const __grid_constant__ CUtensorMap tmB,
    const float* __restrict__ tau_I, const float* __restrict__ tau_T,
    const int* __restrict__ image_ids, const int* __restrict__ text_ids,
    const float* __restrict__ s_I, const float* __restrict__ s_T,
    const float* __restrict__ u_I, const float* __restrict__ u_T,
    const float* __restrict__ b_I, const float* __restrict__ b_T,
    float* __restrict__ out)
{
#if HAS_TC
    extern __shared__ __align__(1024) char smem[];
    const int tid = threadIdx.x;

    if (blockIdx.x < NCPB) {   // state copy (dst 4B-aligned: scalar stores)
        const float* srcs[8] = {s_I, s_T, u_I, u_T, b_I, b_T, tau_I, tau_T};
        const int g0 = blockIdx.x * 128 + tid, stride = NCPB * 128;
#pragma unroll
        for (int a = 0; a < 8; a++) {
            const float4* src = (const float4*)srcs[a];
            float* dst = out + O_STATE + (size_t)a * NST;
            for (int i4 = g0; i4 < NST / 4; i4 += stride) {
                float4 v = src[i4];
                float* d = dst + (size_t)i4 * 4;
                d[0] = v.x; d[1] = v.y; d[2] = v.z; d[3] = v.w;
            }
        }
        return;
    }

    const uint32_t sb = smem_u32(smem);
    const int wid = tid >> 5;
    const int bid = blockIdx.x - NCPB;
    const int bx = bid & (NBX - 1), by = bid >> 4;
    const int m0 = by * MT, n0 = bx * NTL;

    if (wid == 0) { TCG_ALLOC(sb + SM_TMEM, 256); TCG_RELINQ(); }
    if (tid == 0) {
        MBAR_INIT(sb + SM_FULL(0), 1);  MBAR_INIT(sb + SM_FULL(1), 1);
        MBAR_INIT(sb + SM_EMPTY(0), 1); MBAR_INIT(sb + SM_EMPTY(1), 1);
        MBAR_INIT(sb + SM_DONE, 1);
    }
    __syncthreads();
    uint32_t tmem;
    asm volatile("ld.shared.b32 %0, [%1];" : "=r"(tmem) : "r"(sb + SM_TMEM));

    if (tid >= 64) {           // warps 2-3: stage inverse taus
        int q = tid - 64;
        float* itt = (float*)(smem + SM_ITT);
        float* itr = (float*)(smem + SM_ITR);
#pragma unroll
        for (int k = 0; k < 4; k++) itt[q + 64 * k] = 1.0f / tau_T[text_ids[n0 + q + 64 * k]];
#pragma unroll
        for (int k = 0; k < 2; k++) itr[q + 64 * k] = 1.0f / tau_I[image_ids[m0 + q + 64 * k]];
    }

    if (wid == 0 && (tid & 31) == 0) {            // producer (TMA)
        int ph = 1;
        for (int t = 0; t < NSTAGE; t++) {
            int s = t & 1;
            mbar_wait(sb + SM_EMPTY(s), (uint32_t)ph);
            if (s == 1) ph ^= 1;
            MBAR_EXPECT_TX(sb + SM_FULL(s), STAGE_BYTES);
            TMA2D(sb + SM_A(s), &tmA, t * 16, m0, sb + SM_FULL(s));
            TMA2D(sb + SM_B(s), &tmB, t * 16, n0, sb + SM_FULL(s));
        }
    } else if (wid == 1 && (tid & 31) == 0) {     // MMA issuer
        int ph = 0;
        for (int t = 0; t < NSTAGE; t++) {
            int s = t & 1;
            mbar_wait(sb + SM_FULL(s), (uint32_t)ph);
            if (s == 1) ph ^= 1;
            uint64_t ad = smem_desc_sw64(sb + SM_A(s));
            uint64_t bd = smem_desc_sw64(sb + SM_B(s));
#pragma unroll
            for (int k = 0; k < 2; k++)
                mma_tf32_ss(tmem, ad + k * 2, bd + k * 2, (t | k) != 0);
            TCG_COMMIT(sb + SM_EMPTY(s));
        }
        TCG_COMMIT(sb + SM_DONE);
    }

    mbar_wait(sb + SM_DONE, 0);
    TCG_FENCE_AFTER();
    __syncthreads();

    // ---- fused epilogue (row + col online-softmax partials) ----
    const float invR = ((float*)(smem + SM_ITR))[tid];
    float* itt = (float*)(smem + SM_ITT);
    float* smT = (float*)(smem + SM_T);          // [128][33]
    float* pmM = (float*)(smem + SM_PM);
    float* pmS = (float*)(smem + SM_PS);
    float* pmW = (float*)(smem + SM_PW);
    const int cb_d = (bx == (by >> 1)) ? ((m0 + tid - n0) >> 5) : -1;
    const int j0 = (m0 + tid - n0) & 31;

    float rm = -1e30f, rS = 0.f, rW = 0.f;
    for (int cb = 0; cb < 8; cb++) {
        uint32_t dr[32];
        LDTM_X32(dr, tmem + cb * 32);
        TCG_WAIT_LD();

        float mx = __uint_as_float(dr[0]);
#pragma unroll
        for (int j = 1; j < 32; j++) mx = fmaxf(mx, __uint_as_float(dr[j]));
        float cm = mx * invR;
        if (cm > rm) { float sc = __expf(rm - cm); rS *= sc; rW *= sc; rm = cm; }
#pragma unroll
        for (int j = 0; j < 32; j++) {
            float y = __uint_as_float(dr[j]) * invR;
            float e = __expf(y - rm);
            rS += e; rW += e * y;
        }
#pragma unroll
        for (int j = 0; j < 32; j++) smT[tid * 33 + j] = __uint_as_float(dr[j]);
        __syncthreads();
        if (cb == cb_d) g_diag[m0 + tid] = smT[tid * 33 + j0];
        {
            int j = tid & 31, rg = tid >> 5;
            float it = itt[cb * 32 + j];
            float cmx = -1e30f;
#pragma unroll
            for (int i = 0; i < 32; i++) cmx = fmaxf(cmx, smT[(rg * 32 + i) * 33 + j]);
            cmx *= it;
            float S2 = 0.f, W2 = 0.f;
#pragma unroll
            for (int i = 0; i < 32; i++) {
                float y = smT[(rg * 32 + i) * 33 + j] * it;
                float e = __expf(y - cmx);
                S2 += e; W2 += e * y;
            }
            pmM[rg * 32 + j] = cmx; pmS[rg * 32 + j] = S2; pmW[rg * 32 + j] = W2;
        }
        __syncthreads();
        if (tid < 32) {
            float m = pmM[tid], S = pmS[tid], W = pmW[tid];
#pragma unroll
            for (int rg = 1; rg < 4; rg++)
                omerge(m, S, W, pmM[rg * 32 + tid], pmS[rg * 32 + tid], pmW[rg * 32 + tid]);
            size_t o = (size_t)(n0 + cb * 32 + tid) * NBY + by;
            g_colM[o] = m; g_colS[o] = S; g_colW[o] = W;
        }
        __syncthreads();
    }
    {
        size_t o = (size_t)(m0 + tid) * NBX + bx;
        g_rowM[o] = rm; g_rowS[o] = rS; g_rowW[o] = rW;
    }
    __syncthreads();
    if (wid == 0) TCG_DEALLOC(tmem, 256);
#endif  // HAS_TC
}

// ---- tc merge ----
__global__ void __launch_bounds__(256) merge_tc(
    const float* __restrict__ tau_I, const float* __restrict__ s_I,
    const float* __restrict__ u_I, const float* __restrict__ b_I,
    const float* __restrict__ tau_T, const float* __restrict__ s_T,
    const float* __restrict__ u_T, const float* __restrict__ b_T,
    const int* __restrict__ image_ids, const int* __restrict__ text_ids,
    const int* __restrict__ epoch, const int* __restrict__ max_epoch,
    float* __restrict__ out)
{
    const bool is_col = blockIdx.x >= (BSZ / 8);
    const int base = is_col ? blockIdx.x - BSZ / 8 : blockIdx.x;
    const int i = base * 8 + (threadIdx.x >> 5);
    const int lane = threadIdx.x & 31;
    const int np = is_col ? NBY : NBX;

    const float* gM = is_col ? g_colM : g_rowM;
    const float* gS = is_col ? g_colS : g_rowS;
    const float* gW = is_col ? g_colW : g_rowW;
    const int* ids = is_col ? text_ids : image_ids;
    const float* tauA = is_col ? tau_T : tau_I;
    const float* sA = is_col ? s_T : s_I;
    const float* uA = is_col ? u_T : u_I;
    const float* bA = is_col ? b_T : b_I;

    bool act = lane < np;
    float m = act ? gM[i * np + lane] : -1e30f;
    float S = act ? gS[i * np + lane] : 0.f;
    float W = act ? gW[i * np + lane] : 0.f;
    float M = m;
#pragma unroll
    for (int o = 16; o; o >>= 1) M = fmaxf(M, __shfl_xor_sync(0xffffffffu, M, o));
    const int id = ids[i];
    const float tau = tauA[id];
    const float d = g_diag[i] / tau;
    const float old_b = bA[id];
    const float new_b = fmaxf(M - d, old_b);
    float e = act ? __expf(m - d - new_b) : 0.f;
    float Sx = S * e;
    float Wx = (W - d * S) * e;
#pragma unroll
    for (int o = 16; o; o >>= 1) {
        Sx += __shfl_xor_sync(0xffffffffu, Sx, o);
        Wx += __shfl_xor_sync(0xffffffffu, Wx, o);
    }
    if (lane == 0) {
        const float gv = Sx / (float)(BSZ - 1);
        const float s_new = (1.f - GAMMA_S) * sA[id] * expf(old_b - new_b) + GAMMA_S * gv;
        const float wsum = Wx / (s_new + EPS_) / (float)(BSZ - 1);
        const float loss = tau * wsum;
        const float grad = logf(s_new) + new_b + RHO - wsum;
        const float gclip = fminf(fmaxf(grad, -GRAD_CLIP_), GRAD_CLIP_);
        const float u_new = (1.f - GAMMA_U) * uA[id] + GAMMA_U * gclip;
        const float eta = eta_of(*epoch, *max_epoch);
        const float tau_new = fminf(fmaxf(tau - eta * u_new, TAU_MIN_), TAU_MAX_);
        if (!is_col) {
            out[OG_I + i] = gv;   out[OGR_I + i] = grad;
            g_loss_img[i] = loss; g_tau_img[i] = tau;
            out[O_SI + id] = s_new;  out[O_BI + id] = new_b;
            out[O_UI + id] = u_new;  out[O_TAUI + id] = tau_new;
        } else {
            out[OG_T + i] = gv;   out[OGR_T + i] = grad;
            g_loss_txt[i] = loss; g_tau_txt[i] = tau;
            out[O_ST + id] = s_new;  out[O_BT + id] = new_b;
            out[O_UT + id] = u_new;  out[O_TAUT + id] = tau_new;
        }
    }
}

// ---- finalize: vectorized, deterministic ----
__global__ void __launch_bounds__(256) finalize_tc(float* __restrict__ out)
{
    __shared__ float r0[8], r1[8], r2[8], r3[8];
    const int tid = threadIdx.x;
    float sli = 0.f, slt = 0.f, sti = 0.f, stt = 0.f;
    const float4* LI = (const float4*)g_loss_img;
    const float4* LT = (const float4*)g_loss_txt;
    const float4* TI = (const float4*)g_tau_img;
    const float4* TT = (const float4*)g_tau_txt;
#pragma unroll
    for (int k = 0; k < 4; k++) {
        int idx = tid + k * 256;
        float4 a = LI[idx]; sli += (a.x + a.y) + (a.z + a.w);
        float4 b = LT[idx]; slt += (b.x + b.y) + (b.z + b.w);
        float4 c = TI[idx]; sti += (c.x + c.y) + (c.z + c.w);
        float4 d = TT[idx]; stt += (d.x + d.y) + (d.z + d.w);
    }
#pragma unroll
    for (int o = 16; o; o >>= 1) {
        sli += __shfl_xor_sync(0xffffffffu, sli, o);
        slt += __shfl_xor_sync(0xffffffffu, slt, o);
        sti += __shfl_xor_sync(0xffffffffu, sti, o);
        stt += __shfl_xor_sync(0xffffffffu, stt, o);
    }
    if ((tid & 31) == 0) {
        r0[tid >> 5] = sli; r1[tid >> 5] = slt;
        r2[tid >> 5] = sti; r3[tid >> 5] = stt;
    }
    __syncthreads();
    if (tid == 0) {
        float a = 0.f, b = 0.f, c = 0.f, d = 0.f;
#pragma unroll
        for (int w = 0; w < 8; w++) { a += r0[w]; b += r1[w]; c += r2[w]; d += r3[w]; }
        out[O_LOSS] = a / (float)BSZ + b / (float)BSZ;
        out[O_AVGI] = c / (float)BSZ;
        out[O_AVGT] = d / (float)BSZ;
    }
}

// =====================================================================
// ================  FALLBACK PATH (Round-6, proven)  ==================
// =====================================================================

__device__ __forceinline__ void mma_tf32(float* c, uint32_t a0, uint32_t a1,
                                         uint32_t a2, uint32_t a3,
                                         uint32_t b0, uint32_t b1) {
    asm volatile(
        "mma.sync.aligned.m16n8k8.row.col.f32.tf32.tf32.f32 "
        "{%0,%1,%2,%3}, {%4,%5,%6,%7}, {%8,%9}, {%0,%1,%2,%3};"
        : "+f"(c[0]), "+f"(c[1]), "+f"(c[2]), "+f"(c[3])
        : "r"(a0), "r"(a1), "r"(a2), "r"(a3), "r"(b0), "r"(b1));
}

struct SGemm { uint32_t As[4][128][20]; uint32_t Bs[4][128][20]; };
struct SEpi {
    float tauR[128], tauT[128];
    float pm[128][4], pS[128][4], pW[128][4];
    float cm[128][2], cS[128][2], cW[128][2];
};
union SUF { SGemm g; SEpi e; };

__global__ void __launch_bounds__(256) convert_pack(
    const float* __restrict__ A, const float* __restrict__ Bm)
{
    size_t idx = (size_t)blockIdx.x * 256 + threadIdx.x;
    const float* src;
    uint32_t* dst;
    if (idx < NCHUNK) { src = A; dst = g_A32; }
    else { idx -= NCHUNK; src = Bm; dst = g_B32; }

    const float4* s4 = (const float4*)src + idx * 4;
    float4 v0 = s4[0], v1 = s4[1], v2 = s4[2], v3 = s4[3];

    uint4 o0 = make_uint4(f2tf32(v0.x), f2tf32(v1.x), f2tf32(v0.y), f2tf32(v1.y));
    uint4 o1 = make_uint4(f2tf32(v0.z), f2tf32(v1.z), f2tf32(v0.w), f2tf32(v1.w));
    uint4 o2 = make_uint4(f2tf32(v2.x), f2tf32(v3.x), f2tf32(v2.y), f2tf32(v3.y));
    uint4 o3 = make_uint4(f2tf32(v2.z), f2tf32(v3.z), f2tf32(v2.w), f2tf32(v3.w));

    uint4* d4 = (uint4*)dst + idx * 4;
    d4[0] = o0; d4[1] = o1; d4[2] = o2; d4[3] = o3;
}

__global__ void __launch_bounds__(256, 2) gemm_fused(
    const float* __restrict__ tau_I, const float* __restrict__ tau_T,
    const int* __restrict__ image_ids, const int* __restrict__ text_ids,
    const float* __restrict__ s_I, const float* __restrict__ s_T,
    const float* __restrict__ u_I, const float* __restrict__ u_T,
    const float* __restrict__ b_I, const float* __restrict__ b_T,
    float* __restrict__ out)
{
    extern __shared__ __align__(16) char smbuf[];
    SUF& sm = *reinterpret_cast<SUF*>(smbuf);

    const int tid = threadIdx.x;

    if (blockIdx.x < NCOPY) {
        const float* srcs[8] = {s_I, s_T, u_I, u_T, b_I, b_T, tau_I, tau_T};
        const int gtid = blockIdx.x * 256 + tid;
        const int stride = NCOPY * 256;
#pragma unroll
        for (int a = 0; a < 8; a++) {
            const float4* src = (const float4*)srcs[a];
            float* dst = out + O_STATE + (size_t)a * NST;
            for (int i4 = gtid; i4 < NST / 4; i4 += stride) {
                float4 v = src[i4];
                float* d = dst + (size_t)i4 * 4;
                d[0] = v.x; d[1] = v.y; d[2] = v.z; d[3] = v.w;
            }
        }
        return;
    }

    const int bid = blockIdx.x - NCOPY;
    const int bx = bid & 31, by = bid >> 5;
    const int lane = tid & 31, wid = tid >> 5;
    const int m0 = by * 128, n0 = bx * 128;
    const int wm = (wid & 1) * 64, wn = (wid >> 1) * 32;
    const int g = lane >> 2, t4 = lane & 3;

    float acc[4][4][4];
#pragma unroll
    for (int a = 0; a < 4; a++)
#pragma unroll
        for (int b = 0; b < 4; b++)
#pragma unroll
            for (int r = 0; r < 4; r++) acc[a][b][r] = 0.f;

    auto load_stage = [&](int s, int k0, bool valid) {
        if (valid) {
#pragma unroll
            for (int it = 0; it < 2; it++) {
                int f = tid + it * 256;
                int r = f >> 2, kq = (f & 3) * 4;
                uint32_t da = (uint32_t)__cvta_generic_to_shared(&sm.g.As[s][r][kq]);
                const uint32_t* pa = g_A32 + (size_t)(m0 + r) * DIM + k0 + kq;
                asm volatile("cp.async.cg.shared.global [%0], [%1], 16;\n"
                             :: "r"(da), "l"(pa) : "memory");
                uint32_t db = (uint32_t)__cvta_generic_to_shared(&sm.g.Bs[s][r][kq]);
                const uint32_t* pb = g_B32 + (size_t)(n0 + r) * DIM + k0 + kq;
                asm volatile("cp.async.cg.shared.global [%0], [%1], 16;\n"
                             :: "r"(db), "l"(pb) : "memory");
            }
        }
        asm volatile("cp.async.commit_group;\n" ::: "memory");
    };

    auto compute_stage = [&](int s) {
#pragma unroll
        for (int ks = 0; ks < 2; ks++) {
            const int col = ks * 8 + 2 * t4;
            uint32_t af[4][4], bf[4][2];
#pragma unroll
            for (int mt = 0; mt < 4; mt++) {
                int mb = wm + mt * 16 + g;
                uint2 lo = *(const uint2*)&sm.g.As[s][mb][col];
                uint2 hi = *(const uint2*)&sm.g.As[s][mb + 8][col];
                af[mt][0] = lo.x; af[mt][2] = lo.y;
                af[mt][1] = hi.x; af[mt][3] = hi.y;
            }
#pragma unroll
            for (int nt = 0; nt < 4; nt++) {
                int nb = wn + nt * 8 + g;
                uint2 vb = *(const uint2*)&sm.g.Bs[s][nb][col];
                bf[nt][0] = vb.x; bf[nt][1] = vb.y;
            }
#pragma unroll
            for (int mt = 0; mt < 4; mt++)
#pragma unroll
                for (int nt = 0; nt < 4; nt++)
                    mma_tf32(acc[mt][nt], af[mt][0], af[mt][1], af[mt][2],
                             af[mt][3], bf[nt][0], bf[nt][1]);
        }
    };

    load_stage(0, 0, true);
    load_stage(1, 16, true);
    load_stage(2, 32, true);
#pragma unroll 1
    for (int kt = 0; kt < 64; kt++) {
        asm volatile("cp.async.wait_group 2;\n" ::: "memory");
        __syncthreads();
        int nx = kt + 3;
        load_stage(nx & 3, nx * 16, nx < 64);
        compute_stage(kt & 3);
    }
    __syncthreads();

    if (bx == by) {
#pragma unroll
        for (int mt = 0; mt < 4; mt++)
#pragma unroll
            for (int nt = 0; nt < 4; nt++)
#pragma unroll
                for (int h = 0; h < 2; h++)
#pragma unroll
                    for (int ci = 0; ci < 2; ci++) {
                        int rl = wm + mt * 16 + g + 8 * h;
                        int cl = wn + nt * 8 + t4 * 2 + ci;
                        if (rl == cl) g_diag[m0 + rl] = acc[mt][nt][2 * h + ci];
                    }
    }

    if (tid < 128) sm.e.tauR[tid] = tau_I[image_ids[m0 + tid]];
    else           sm.e.tauT[tid - 128] = tau_T[text_ids[n0 + tid - 128]];
    __syncthreads();

#pragma unroll
    for (int mt = 0; mt < 4; mt++) {
#pragma unroll
        for (int h = 0; h < 2; h++) {
            int rl = wm + mt * 16 + g + 8 * h;
            float inv = 1.0f / sm.e.tauR[rl];
            float y[8];
#pragma unroll
            for (int nt = 0; nt < 4; nt++) {
                y[nt * 2]     = acc[mt][nt][2 * h] * inv;
                y[nt * 2 + 1] = acc[mt][nt][2 * h + 1] * inv;
            }
            float m = y[0];
#pragma unroll
            for (int q = 1; q < 8; q++) m = fmaxf(m, y[q]);
            float S = 0.f, W = 0.f;
#pragma unroll
            for (int q = 0; q < 8; q++) {
                float e = __expf(y[q] - m);
                S += e; W += e * y[q];
            }
#pragma unroll
            for (int o = 1; o <= 2; o <<= 1) {
                float om = __shfl_xor_sync(0xffffffffu, m, o);
                float oS = __shfl_xor_sync(0xffffffffu, S, o);
                float oW = __shfl_xor_sync(0xffffffffu, W, o);
                omerge(m, S, W, om, oS, oW);
            }
            if (t4 == 0) {
                sm.e.pm[rl][wid >> 1] = m;
                sm.e.pS[rl][wid >> 1] = S;
                sm.e.pW[rl][wid >> 1] = W;
            }
        }
    }

#pragma unroll
    for (int nt = 0; nt < 4; nt++) {
#pragma unroll
        for (int ci = 0; ci < 2; ci++) {
            int cl = wn + nt * 8 + t4 * 2 + ci;
            float inv = 1.0f / sm.e.tauT[cl];
            float y[8];
#pragma unroll
            for (int mt = 0; mt < 4; mt++) {
                y[mt * 2]     = acc[mt][nt][ci] * inv;
                y[mt * 2 + 1] = acc[mt][nt][2 + ci] * inv;
            }
            float m = y[0];
#pragma unroll
            for (int q = 1; q < 8; q++) m = fmaxf(m, y[q]);
            float S = 0.f, W = 0.f;
#pragma unroll
            for (int q = 0; q < 8; q++) {
                float e = __expf(y[q] - m);
                S += e; W += e * y[q];
            }
#pragma unroll
            for (int o = 4; o <= 16; o <<= 1) {
                float om = __shfl_xor_sync(0xffffffffu, m, o);
                float oS = __shfl_xor_sync(0xffffffffu, S, o);
                float oW = __shfl_xor_sync(0xffffffffu, W, o);
                omerge(m, S, W, om, oS, oW);
            }
            if (g == 0) {
                sm.e.cm[cl][wid & 1] = m;
                sm.e.cS[cl][wid & 1] = S;
                sm.e.cW[cl][wid & 1] = W;
            }
        }
    }
    __syncthreads();

    if (tid < 128) {
        float m = sm.e.pm[tid][0], S = sm.e.pS[tid][0], W = sm.e.pW[tid][0];
#pragma unroll
        for (int p = 1; p < 4; p++)
            omerge(m, S, W, sm.e.pm[tid][p], sm.e.pS[tid][p], sm.e.pW[tid][p]);
        size_t o = (size_t)(m0 + tid) * 32 + bx;
        g_rowM[o] = m; g_rowS[o] = S; g_rowW[o] = W;

        float m2 = sm.e.cm[tid][0], S2 = sm.e.cS[tid][0], W2 = sm.e.cW[tid][0];
        omerge(m2, S2, W2, sm.e.cm[tid][1], sm.e.cS[tid][1], sm.e.cW[tid][1]);
        size_t o2 = (size_t)(n0 + tid) * 32 + by;
        g_colM[o2] = m2; g_colS[o2] = S2; g_colW[o2] = W2;
    }
}

__global__ void __launch_bounds__(256) merge_fb(
    const float* __restrict__ tau_I, const float* __restrict__ s_I,
    const float* __restrict__ u_I, const float* __restrict__ b_I,
    const float* __restrict__ tau_T, const float* __restrict__ s_T,
    const float* __restrict__ u_T, const float* __restrict__ b_T,
    const int* __restrict__ image_ids, const int* __restrict__ text_ids,
    const int* __restrict__ epoch, const int* __restrict__ max_epoch,
    float* __restrict__ out)
{
    const bool is_col = blockIdx.x >= (BSZ / 8);
    const int base = is_col ? blockIdx.x - BSZ / 8 : blockIdx.x;
    const int i = base * 8 + (threadIdx.x >> 5);
    const int lane = threadIdx.x & 31;

    const float* gM = is_col ? g_colM : g_rowM;
    const float* gS = is_col ? g_colS : g_rowS;
    const float* gW = is_col ? g_colW : g_rowW;
    const int* ids = is_col ? text_ids : image_ids;
    const float* tauA = is_col ? tau_T : tau_I;
    const float* sA = is_col ? s_T : s_I;
    const float* uA = is_col ? u_T : u_I;
    const float* bA = is_col ? b_T : b_I;

    float m = gM[i * 32 + lane];
    float S = gS[i * 32 + lane];
    float W = gW[i * 32 + lane];
    float M = m;
#pragma unroll
    for (int o = 16; o; o >>= 1) M = fmaxf(M, __shfl_xor_sync(0xffffffffu, M, o));
    const int id = ids[i];
    const float tau = tauA[id];
    const float d = g_diag[i] / tau;
    const float old_b = bA[id];
    const float new_b = fmaxf(M - d, old_b);
    float e = __expf(m - d - new_b);
    float Sx = S * e;
    float Wx = (W - d * S) * e;
#pragma unroll
    for (int o = 16; o; o >>= 1) {
        Sx += __shfl_xor_sync(0xffffffffu, Sx, o);
        Wx += __shfl_xor_sync(0xffffffffu, Wx, o);
    }
    if (lane == 0) {
        const float gv = Sx / (float)(BSZ - 1);
        const float s_new = (1.f - GAMMA_S) * sA[id] * expf(old_b - new_b) + GAMMA_S * gv;
        const float wsum = Wx / (s_new + EPS_) / (float)(BSZ - 1);
        const float loss = tau * wsum;
        const float grad = logf(s_new) + new_b + RHO - wsum;
        const float gclip = fminf(fmaxf(grad, -GRAD_CLIP_), GRAD_CLIP_);
        const float u_new = (1.f - GAMMA_U) * uA[id] + GAMMA_U * gclip;
        const float eta = eta_of(*epoch, *max_epoch);
        const float tau_new = fminf(fmaxf(tau - eta * u_new, TAU_MIN_), TAU_MAX_);
        if (!is_col) {
            out[OG_I + i] = gv;   out[OGR_I + i] = grad;
            g_loss_img[i] = loss; g_tau_img[i] = tau;
            out[O_SI + id] = s_new;  out[O_BI + id] = new_b;
            out[O_UI + id] = u_new;  out[O_TAUI + id] = tau_new;
        } else {
            out[OG_T + i] = gv;   out[OGR_T + i] = grad;
            g_loss_txt[i] = loss; g_tau_txt[i] = tau;
            out[O_ST + id] = s_new;  out[O_BT + id] = new_b;
            out[O_UT + id] = u_new;  out[O_TAUT + id] = tau_new;
        }
    }
}

// ===================== launch =====================

typedef CUresult (*PFN_tmap)(CUtensorMap*, CUtensorMapDataType, cuuint32_t, void*,
                             const cuuint64_t*, const cuuint64_t*, const cuuint32_t*,
                             const cuuint32_t*, CUtensorMapInterleave, CUtensorMapSwizzle,
                             CUtensorMapL2promotion, CUtensorMapFloatOOBfill);

extern "C" void kernel_launch(void* const* d_in, const int* in_sizes, int n_in,
                              void* d_out, int out_size)
{
    const float* imf   = (const float*)d_in[0];
    const float* txf   = (const float*)d_in[1];
    const float* s_I   = (const float*)d_in[2];
    const float* s_T   = (const float*)d_in[3];
    const float* tau_I = (const float*)d_in[4];
    const float* tau_T = (const float*)d_in[5];
    const float* u_I   = (const float*)d_in[6];
    const float* u_T   = (const float*)d_in[7];
    const float* b_I   = (const float*)d_in[8];
    const float* b_T   = (const float*)d_in[9];
    const int* image_ids = (const int*)d_in[10];
    const int* text_ids  = (const int*)d_in[11];
    const int* epoch     = (const int*)d_in[12];
    const int* max_epoch = (const int*)d_in[13];
    float* out = (float*)d_out;

    static CUtensorMap tmA, tmB;
    static int use_tc = -1;
    if (use_tc < 0) {
        cudaFuncSetAttribute(gemm_fused, cudaFuncAttributeMaxDynamicSharedMemorySize,
                             (int)sizeof(SUF));
        cudaFuncSetAttribute(gemm_tc, cudaFuncAttributeMaxDynamicSharedMemorySize, SMEM_TC);
        int v = 0;
        cudaMemcpyFromSymbol(&v, g_use_tc, sizeof(int));
        if (v) {
            void* fp = nullptr;
            cudaDriverEntryPointQueryResult qr;
            cudaGetDriverEntryPoint("cuTensorMapEncodeTiled", &fp, cudaEnableDefault, &qr);
            PFN_tmap enc = (PFN_tmap)fp;
            if (!enc) v = 0;
            else {
                void *pA, *pB;
                cudaGetSymbolAddress(&pA, g_A32);
                cudaGetSymbolAddress(&pB, g_B32);
                cuuint64_t dims[2] = {DIM, BSZ};
                cuuint64_t strides[1] = {DIM * 4};
                cuuint32_t boxA[2] = {16, MT}, boxB[2] = {16, NTL}, es[2] = {1, 1};
                CUresult r1 = enc(&tmA, CU_TENSOR_MAP_DATA_TYPE_FLOAT32, 2, pA, dims, strides,
                                  boxA, es, CU_TENSOR_MAP_INTERLEAVE_NONE,
                                  CU_TENSOR_MAP_SWIZZLE_64B,
                                  CU_TENSOR_MAP_L2_PROMOTION_L2_128B,
                                  CU_TENSOR_MAP_FLOAT_OOB_FILL_NONE);
                CUresult r2 = enc(&tmB, CU_TENSOR_MAP_DATA_TYPE_FLOAT32, 2, pB, dims, strides,
                                  boxB, es, CU_TENSOR_MAP_INTERLEAVE_NONE,
                                  CU_TENSOR_MAP_SWIZZLE_64B,
                                  CU_TENSOR_MAP_L2_PROMOTION_L2_128B,
                                  CU_TENSOR_MAP_FLOAT_OOB_FILL_NONE);
                if (r1 != CUDA_SUCCESS || r2 != CUDA_SUCCESS) v = 0;
            }
        }
        use_tc = v;
    }

    if (use_tc) {
        convert_tf32<<<(2 * BSZ * DIM / 4) / 256, 256>>>(imf, txf);
        gemm_tc<<<NCPB + NBX * NBY, 128, SMEM_TC>>>(
            tmA, tmB, tau_I, tau_T, image_ids, text_ids,
            s_I, s_T, u_I, u_T, b_I, b_T, out);
        merge_tc<<<2 * (BSZ / 8), 256>>>(tau_I, s_I, u_I, b_I,
                                         tau_T, s_T, u_T, b_T,
                                         image_ids, text_ids, epoch, max_epoch, out);
        finalize_tc<<<1, 256>>>(out);
    } else {
        convert_pack<<<2 * NCHUNK / 256, 256>>>(imf, txf);
        gemm_fused<<<NCOPY + 32 * 32, 256, sizeof(SUF)>>>(
            tau_I, tau_T, image_ids, text_ids,
            s_I, s_T, u_I, u_T, b_I, b_T, out);
        merge_fb<<<2 * (BSZ / 8), 256>>>(tau_I, s_I, u_I, b_I,
                                         tau_T, s_T, u_T, b_T,
                                         image_ids, text_ids, epoch, max_epoch, out);
        finalize_tc<<<1, 256>>>(out);
    }
}

// round 12
// speedup vs baseline: 1.1624x; 1.1624x over previous
#include <cuda_runtime.h>
#include <cuda.h>
#include <cstdint>

#define BSZ 4096
#define DIM 1024
#define NST 2900000
#define NCOPY 512
#define NCHUNK ((BSZ * DIM) / 16)

// tc-path tiling: cg2 pair tile 256x256, per-CTA M=128, N=256
#define NBX 16
#define NBY 32
#define NCPB 128
#define NSTAGE 32          // K-chunks of 32

#define GAMMA_S 0.8f
#define GAMMA_U 0.8f
#define RHO 0.1f
#define EPS_ 1e-10f
#define TAU_MIN_ 0.005f
#define TAU_MAX_ 1.0f
#define GRAD_CLIP_ 5.0f
#define ETA_INIT_ 0.01f
#define ETA_MIN_ 0.0001f

#define OG_I   0
#define OG_T   (BSZ)
#define OGR_I  (2*BSZ)
#define OGR_T  (3*BSZ)
#define O_LOSS (4*BSZ)
#define O_AVGI (4*BSZ+1)
#define O_AVGT (4*BSZ+2)
#define O_STATE (4*BSZ+3)
#define O_SI   (O_STATE + 0*NST)
#define O_ST   (O_STATE + 1*NST)
#define O_UI   (O_STATE + 2*NST)
#define O_UT   (O_STATE + 3*NST)
#define O_BI   (O_STATE + 4*NST)
#define O_BT   (O_STATE + 5*NST)
#define O_TAUI (O_STATE + 6*NST)
#define O_TAUT (O_STATE + 7*NST)

#if defined(__CUDA_ARCH_FEAT_SM103_ALL) || defined(__CUDA_ARCH_FEAT_SM100_ALL) || defined(__CUDA_ARCH_FEAT_SM101_ALL)
#define HAS_TC 1
#else
#define HAS_TC 0
#endif

__device__ int g_use_tc = HAS_TC;

// ----- shared scratch -----
__device__ uint32_t g_A32[(size_t)BSZ * DIM];
__device__ uint32_t g_B32[(size_t)BSZ * DIM];
__device__ float g_rowM[BSZ * 32], g_rowS[BSZ * 32], g_rowW[BSZ * 32];
__device__ float g_colM[BSZ * 32], g_colS[BSZ * 32], g_colW[BSZ * 32];
__device__ float g_diag[BSZ];
__device__ float g_loss_img[BSZ], g_loss_txt[BSZ];
__device__ float g_tau_img[BSZ], g_tau_txt[BSZ];

// ===================== common helpers =====================

__device__ __forceinline__ uint32_t f2tf32(float x) {
    uint32_t r; asm("cvt.rna.tf32.f32 %0, %1;" : "=r"(r) : "f"(x)); return r;
}
__device__ __forceinline__ float eta_of(int ep, int mep) {
    float r = (float)ep / (float)mep;
    return ETA_MIN_ + (ETA_INIT_ - ETA_MIN_) * cosf(1.5707963267948966f * r);
}
__device__ __forceinline__ void omerge(float& m, float& S, float& W,
                                       float om, float oS, float oW) {
    float mn = fmaxf(m, om);
    float ea = __expf(m - mn), eb = __expf(om - mn);
    S = S * ea + oS * eb;
    W = W * ea + oW * eb;
    m = mn;
}
__device__ __forceinline__ uint32_t smem_u32(const void* p) {
    uint32_t a;
    asm("{ .reg .u64 t; cvta.to.shared.u64 t, %1; cvt.u32.u64 %0, t; }" : "=r"(a) : "l"(p));
    return a;
}

// =====================================================================
// ======================  TC PATH (sm_103a only)  =====================
// =====================================================================

// smem map: K-chunk 32 (128B rows, SW128), 3-stage ring, per-CTA A/B 16KB each
#define SM_TMEM   0
#define SM_FULL(s)  (8 + (s) * 8)       // 3
#define SM_EMPTY(s) (32 + (s) * 8)      // 3
#define SM_DONE   56
#define SM_ITT    256
#define SM_ITR    1280
#define SM_PM     1792
#define SM_PS     2304
#define SM_PW     2816
#define SM_A(s)   (4096 + (s) * 16384)      // 3 x 16 KB
#define SM_B(s)   (53248 + (s) * 16384)     // 3 x 16 KB
#define SM_T      4096
#define SMEM_TC   102400
#define STAGE_BYTES_PAIR 65536   // A+B from both CTAs per stage

// idesc cg2 kind::tf32: dtype F32(1<<4), a/b TF32(2<<7|2<<10), N=256 (32<<17), M=256 (16<<24)
#define IDESC2 0x10400910u

#if HAS_TC
#define MBAR_INIT(a, c) \
    asm volatile("mbarrier.init.shared.b64 [%0], %1;" :: "r"(a), "r"(c) : "memory")
#define MBAR_EXPECT_TX(a, b) \
    asm volatile("mbarrier.arrive.expect_tx.shared.b64 _, [%0], %1;" :: "r"(a), "r"(b) : "memory")
// cg2 TMA: both CTAs execute; complete_tx targets leader CTA's barrier (bit 24 cleared)
#define TMA2D_CG2(sm, tmap, cx, cy, mb) \
    asm volatile("{\n\t.reg .b32 lb;\n\tand.b32 lb, %4, 0xFEFFFFFF;\n\t" \
        "cp.async.bulk.tensor.2d.cta_group::2.shared::cluster.global.tile.mbarrier::complete_tx::bytes " \
        "[%0], [%1, {%2, %3}], [lb];\n\t}" \
        :: "r"(sm), "l"(tmap), "r"(cx), "r"(cy), "r"(mb) : "memory")
#define TCG_ALLOC2(d, n) \
    asm volatile("tcgen05.alloc.cta_group::2.sync.aligned.shared::cta.b32 [%0], %1;" :: "r"(d), "r"(n) : "memory")
#define TCG_DEALLOC2(a, n) \
    asm volatile("tcgen05.dealloc.cta_group::2.sync.aligned.b32 %0, %1;" :: "r"(a), "r"(n))
#define TCG_RELINQ2() asm volatile("tcgen05.relinquish_alloc_permit.cta_group::2.sync.aligned;")
#define TCG_COMMIT2_MC(mb, mask) \
    asm volatile("tcgen05.commit.cta_group::2.mbarrier::arrive::one.shared::cluster.multicast::cluster.b64 [%0], %1;" \
                 :: "r"(mb), "h"((uint16_t)(mask)) : "memory")
#define TCG_WAIT_LD() asm volatile("tcgen05.wait::ld.sync.aligned;" ::: "memory")
#define TCG_FENCE_AFTER() asm volatile("tcgen05.fence::after_thread_sync;" ::: "memory")
#define CLUSTER_ARRIVE() asm volatile("barrier.cluster.arrive.aligned;" ::: "memory")
#define CLUSTER_WAIT()   asm volatile("barrier.cluster.wait.aligned;" ::: "memory")

__device__ __forceinline__ void mbar_wait(uint32_t mbar, uint32_t par) {
    asm volatile(
        "{\n\t.reg .pred P;\n\tW_%=:\n\t"
        "mbarrier.try_wait.parity.acquire.cta.shared::cta.b64 P, [%0], %1, 0x989680;\n\t"
        "@!P bra W_%=;\n\t}" :: "r"(mbar), "r"(par) : "memory");
}
__device__ __forceinline__ void mma_tf32_cg2(uint32_t d, uint64_t ad, uint64_t bd, uint32_t en) {
    asm volatile(
        "{\n\t.reg .pred p;\n\tsetp.ne.u32 p, %4, 0;\n\t"
        "tcgen05.mma.cta_group::2.kind::tf32 [%0], %1, %2, %3, "
        "{%5,%5,%5,%5,%5,%5,%5,%5}, p;\n\t}"
        :: "r"(d), "l"(ad), "l"(bd), "r"(IDESC2), "r"(en), "r"(0u) : "memory");
}
#define LDTM_X32(r, addr) \
    asm volatile("tcgen05.ld.sync.aligned.32x32b.x32.b32 " \
        "{%0,%1,%2,%3,%4,%5,%6,%7,%8,%9,%10,%11,%12,%13,%14,%15," \
        "%16,%17,%18,%19,%20,%21,%22,%23,%24,%25,%26,%27,%28,%29,%30,%31}, [%32];" \
        : "=r"((r)[0]),"=r"((r)[1]),"=r"((r)[2]),"=r"((r)[3]),"=r"((r)[4]),"=r"((r)[5]), \
          "=r"((r)[6]),"=r"((r)[7]),"=r"((r)[8]),"=r"((r)[9]),"=r"((r)[10]),"=r"((r)[11]), \
          "=r"((r)[12]),"=r"((r)[13]),"=r"((r)[14]),"=r"((r)[15]),"=r"((r)[16]),"=r"((r)[17]), \
          "=r"((r)[18]),"=r"((r)[19]),"=r"((r)[20]),"=r"((r)[21]),"=r"((r)[22]),"=r"((r)[23]), \
          "=r"((r)[24]),"=r"((r)[25]),"=r"((r)[26]),"=r"((r)[27]),"=r"((r)[28]),"=r"((r)[29]), \
          "=r"((r)[30]),"=r"((r)[31]) : "r"(addr))

// SW128 K-major descriptor (validated): layout=2, version=1, SBO=64, LBO=1
static __device__ __forceinline__ uint64_t smem_desc(uint32_t addr) {
    return ((uint64_t)2 << 61) | ((uint64_t)1 << 46) | ((uint64_t)64 << 32) |
           ((uint64_t)1 << 16) | (uint64_t)((addr >> 4) & 0x3FFF);
}
#endif  // HAS_TC

// ---- tc convert ----
__global__ void __launch_bounds__(256) convert_tf32(
    const float* __restrict__ A, const float* __restrict__ Bm)
{
    size_t t = (size_t)blockIdx.x * 256 + threadIdx.x;
    const float* src = A; uint32_t* dst = g_A32;
    if (t >= (1u << 20)) { t -= (1u << 20); src = Bm; dst = g_B32; }
    float4 v = ((const float4*)src)[t];
    ((uint4*)dst)[t] = make_uint4(f2tf32(v.x), f2tf32(v.y), f2tf32(v.z), f2tf32(v.w));
}

// ---- tc GEMM: cg2 pair tiles + fused partials + state copy ----
__global__ void __launch_bounds__(128) gemm_tc(
    const __grid_constant__ CUtensorMap tmA,
    const __grid_constant__ CUtensorMap tmB,
    const float* __restrict__ tau_I, const float* __restrict__ tau_T,
    const int* __restrict__ image_ids, const int* __restrict__ text_ids,
    const float* __restrict__ s_I, const float* __restrict__ s_T,
    const float* __restrict__ u_I, const float* __restrict__ u_T,
    const float* __restrict__ b_I, const float* __restrict__ b_T,
    float* __restrict__ out)
{
#if HAS_TC
    extern __shared__ __align__(1024) char smem[];
    const int tid = threadIdx.x;

    if (blockIdx.x < NCPB) {   // state copy (dst 4B-aligned: scalar stores)
        const float* srcs[8] = {s_I, s_T, u_I, u_T, b_I, b_T, tau_I, tau_T};
        const int g0 = blockIdx.x * 128 + tid, stride = NCPB * 128;
#pragma unroll
        for (int a = 0; a < 8; a++) {
            const float4* src = (const float4*)srcs[a];
            float* dst = out + O_STATE + (size_t)a * NST;
            for (int i4 = g0; i4 < NST / 4; i4 += stride) {
                float4 v = src[i4];
                float* d = dst + (size_t)i4 * 4;
                d[0] = v.x; d[1] = v.y; d[2] = v.z; d[3] = v.w;
            }
        }
        return;
    }

    const uint32_t sb = smem_u32(smem);
    const int wid = tid >> 5;
    uint32_t rank;
    asm("mov.u32 %0, %%cluster_ctarank;" : "=r"(rank));
    const int bid = blockIdx.x - NCPB;       // 0..511
    const int pair = bid >> 1;               // 0..255
    const int bx = pair & (NBX - 1);         // 0..15
    const int byp = pair >> 4;               // 0..15
    const int m0 = byp * 256 + (int)rank * 128;
    const int n0 = bx * 256;
    const int byi = byp * 2 + (int)rank;     // col-partial index 0..31

    if (wid == 0) { TCG_ALLOC2(sb + SM_TMEM, 256); TCG_RELINQ2(); }
    if (tid == 0) {
#pragma unroll
        for (int s = 0; s < 3; s++) {
            MBAR_INIT(sb + SM_FULL(s), 1);
            MBAR_INIT(sb + SM_EMPTY(s), 1);
        }
        MBAR_INIT(sb + SM_DONE, 1);
    }
    __syncthreads();
    CLUSTER_ARRIVE(); CLUSTER_WAIT();   // barriers + alloc visible cluster-wide

    uint32_t tmem;
    asm volatile("ld.shared.b32 %0, [%1];" : "=r"(tmem) : "r"(sb + SM_TMEM));

    if (tid >= 64) {           // warps 2-3: stage inverse taus
        int q = tid - 64;
        float* itt = (float*)(smem + SM_ITT);
        float* itr = (float*)(smem + SM_ITR);
#pragma unroll
        for (int k = 0; k < 4; k++) itt[q + 64 * k] = 1.0f / tau_T[text_ids[n0 + q + 64 * k]];
#pragma unroll
        for (int k = 0; k < 2; k++) itr[q + 64 * k] = 1.0f / tau_I[image_ids[m0 + q + 64 * k]];
    }

    if (wid == 0 && (tid & 31) == 0) {            // producer (both CTAs)
        int st = 0, ph = 1;
        for (int t = 0; t < NSTAGE; t++) {
            mbar_wait(sb + SM_EMPTY(st), (uint32_t)ph);
            if (rank == 0) MBAR_EXPECT_TX(sb + SM_FULL(st), STAGE_BYTES_PAIR);
            TMA2D_CG2(sb + SM_A(st), &tmA, t * 32, m0, sb + SM_FULL(st));
            TMA2D_CG2(sb + SM_B(st), &tmB, t * 32, n0 + (int)rank * 128, sb + SM_FULL(st));
            if (++st == 3) { st = 0; ph ^= 1; }
        }
    } else if (rank == 0 && wid == 1 && (tid & 31) == 0) {   // MMA issuer (leader)
        int st = 0, ph = 0;
        for (int t = 0; t < NSTAGE; t++) {
            mbar_wait(sb + SM_FULL(st), (uint32_t)ph);
            uint64_t ad = smem_desc(sb + SM_A(st));
            uint64_t bd = smem_desc(sb + SM_B(st));
#pragma unroll
            for (int k = 0; k < 4; k++)
                mma_tf32_cg2(tmem, ad + k * 2, bd + k * 2, (t | k) != 0);
            TCG_COMMIT2_MC(sb + SM_EMPTY(st), 0x3);
            if (++st == 3) { st = 0; ph ^= 1; }
        }
        TCG_COMMIT2_MC(sb + SM_DONE, 0x3);
    }

    mbar_wait(sb + SM_DONE, 0);
    TCG_FENCE_AFTER();
    __syncthreads();

    // ---- fused epilogue (per CTA: its 128 rows x 256 cols of D) ----
    const float invR = ((float*)(smem + SM_ITR))[tid];
    float* itt = (float*)(smem + SM_ITT);
    float* smT = (float*)(smem + SM_T);          // [128][33]
    float* pmM = (float*)(smem + SM_PM);
    float* pmS = (float*)(smem + SM_PS);
    float* pmW = (float*)(smem + SM_PW);
    const int cb_d = (bx == byp) ? ((m0 + tid - n0) >> 5) : -1;
    const int j0 = (m0 + tid - n0) & 31;

    float rm = -1e30f, rS = 0.f, rW = 0.f;
    for (int cb = 0; cb < 8; cb++) {
        uint32_t dr[32];
        LDTM_X32(dr, tmem + cb * 32);
        TCG_WAIT_LD();

        float mx = __uint_as_float(dr[0]);
#pragma unroll
        for (int j = 1; j < 32; j++) mx = fmaxf(mx, __uint_as_float(dr[j]));
        float cm = mx * invR;
        if (cm > rm) { float sc = __expf(rm - cm); rS *= sc; rW *= sc; rm = cm; }
#pragma unroll
        for (int j = 0; j < 32; j++) {
            float y = __uint_as_float(dr[j]) * invR;
            float e = __expf(y - rm);
            rS += e; rW += e * y;
        }
#pragma unroll
        for (int j = 0; j < 32; j++) smT[tid * 33 + j] = __uint_as_float(dr[j]);
        __syncthreads();
        if (cb == cb_d) g_diag[m0 + tid] = smT[tid * 33 + j0];
        {
            int j = tid & 31, rg = tid >> 5;
            float it = itt[cb * 32 + j];
            float cmx = -1e30f;
#pragma unroll
            for (int i = 0; i < 32; i++) cmx = fmaxf(cmx, smT[(rg * 32 + i) * 33 + j]);
            cmx *= it;
            float S2 = 0.f, W2 = 0.f;
#pragma unroll
            for (int i = 0; i < 32; i++) {
                float y = smT[(rg * 32 + i) * 33 + j] * it;
                float e = __expf(y - cmx);
                S2 += e; W2 += e * y;
            }
            pmM[rg * 32 + j] = cmx; pmS[rg * 32 + j] = S2; pmW[rg * 32 + j] = W2;
        }
        __syncthreads();
        if (tid < 32) {
            float m = pmM[tid], S = pmS[tid], W = pmW[tid];
#pragma unroll
            for (int rg = 1; rg < 4; rg++)
                omerge(m, S, W, pmM[rg * 32 + tid], pmS[rg * 32 + tid], pmW[rg * 32 + tid]);
            size_t o = (size_t)(n0 + cb * 32 + tid) * NBY + byi;
            g_colM[o] = m; g_colS[o] = S; g_colW[o] = W;
        }
        __syncthreads();
    }
    {
        size_t o = (size_t)(m0 + tid) * NBX + bx;
        g_rowM[o] = rm; g_rowS[o] = rS; g_rowW[o] = rW;
    }
    __syncthreads();
    CLUSTER_ARRIVE(); CLUSTER_WAIT();   // peer may still read my smem via cg2 MMA
    if (wid == 0) TCG_DEALLOC2(tmem, 256);
#endif  // HAS_TC
}

// ---- tc merge ----
__global__ void __launch_bounds__(256) merge_tc(
    const float* __restrict__ tau_I, const float* __restrict__ s_I,
    const float* __restrict__ u_I, const float* __restrict__ b_I,
    const float* __restrict__ tau_T, const float* __restrict__ s_T,
    const float* __restrict__ u_T, const float* __restrict__ b_T,
    const int* __restrict__ image_ids, const int* __restrict__ text_ids,
    const int* __restrict__ epoch, const int* __restrict__ max_epoch,
    float* __restrict__ out)
{
    const bool is_col = blockIdx.x >= (BSZ / 8);
    const int base = is_col ? blockIdx.x - BSZ / 8 : blockIdx.x;
    const int i = base * 8 + (threadIdx.x >> 5);
    const int lane = threadIdx.x & 31;
    const int np = is_col ? NBY : NBX;

    const float* gM = is_col ? g_colM : g_rowM;
    const float* gS = is_col ? g_colS : g_rowS;
    const float* gW = is_col ? g_colW : g_rowW;
    const int* ids = is_col ? text_ids : image_ids;
    const float* tauA = is_col ? tau_T : tau_I;
    const float* sA = is_col ? s_T : s_I;
    const float* uA = is_col ? u_T : u_I;
    const float* bA = is_col ? b_T : b_I;

    bool act = lane < np;
    float m = act ? gM[i * np + lane] : -1e30f;
    float S = act ? gS[i * np + lane] : 0.f;
    float W = act ? gW[i * np + lane] : 0.f;
    float M = m;
#pragma unroll
    for (int o = 16; o; o >>= 1) M = fmaxf(M, __shfl_xor_sync(0xffffffffu, M, o));
    const int id = ids[i];
    const float tau = tauA[id];
    const float d = g_diag[i] / tau;
    const float old_b = bA[id];
    const float new_b = fmaxf(M - d, old_b);
    float e = act ? __expf(m - d - new_b) : 0.f;
    float Sx = S * e;
    float Wx = (W - d * S) * e;
#pragma unroll
    for (int o = 16; o; o >>= 1) {
        Sx += __shfl_xor_sync(0xffffffffu, Sx, o);
        Wx += __shfl_xor_sync(0xffffffffu, Wx, o);
    }
    if (lane == 0) {
        const float gv = Sx / (float)(BSZ - 1);
        const float s_new = (1.f - GAMMA_S) * sA[id] * expf(old_b - new_b) + GAMMA_S * gv;
        const float wsum = Wx / (s_new + EPS_) / (float)(BSZ - 1);
        const float loss = tau * wsum;
        const float grad = logf(s_new) + new_b + RHO - wsum;
        const float gclip = fminf(fmaxf(grad, -GRAD_CLIP_), GRAD_CLIP_);
        const float u_new = (1.f - GAMMA_U) * uA[id] + GAMMA_U * gclip;
        const float eta = eta_of(*epoch, *max_epoch);
        const float tau_new = fminf(fmaxf(tau - eta * u_new, TAU_MIN_), TAU_MAX_);
        if (!is_col) {
            out[OG_I + i] = gv;   out[OGR_I + i] = grad;
            g_loss_img[i] = loss; g_tau_img[i] = tau;
            out[O_SI + id] = s_new;  out[O_BI + id] = new_b;
            out[O_UI + id] = u_new;  out[O_TAUI + id] = tau_new;
        } else {
            out[OG_T + i] = gv;   out[OGR_T + i] = grad;
            g_loss_txt[i] = loss; g_tau_txt[i] = tau;
            out[O_ST + id] = s_new;  out[O_BT + id] = new_b;
            out[O_UT + id] = u_new;  out[O_TAUT + id] = tau_new;
        }
    }
}

// ---- finalize: vectorized, deterministic ----
__global__ void __launch_bounds__(256) finalize_tc(float* __restrict__ out)
{
    __shared__ float r0[8], r1[8], r2[8], r3[8];
    const int tid = threadIdx.x;
    float sli = 0.f, slt = 0.f, sti = 0.f, stt = 0.f;
    const float4* LI = (const float4*)g_loss_img;
    const float4* LT = (const float4*)g_loss_txt;
    const float4* TI = (const float4*)g_tau_img;
    const float4* TT = (const float4*)g_tau_txt;
#pragma unroll
    for (int k = 0; k < 4; k++) {
        int idx = tid + k * 256;
        float4 a = LI[idx]; sli += (a.x + a.y) + (a.z + a.w);
        float4 b = LT[idx]; slt += (b.x + b.y) + (b.z + b.w);
        float4 c = TI[idx]; sti += (c.x + c.y) + (c.z + c.w);
        float4 d = TT[idx]; stt += (d.x + d.y) + (d.z + d.w);
    }
#pragma unroll
    for (int o = 16; o; o >>= 1) {
        sli += __shfl_xor_sync(0xffffffffu, sli, o);
        slt += __shfl_xor_sync(0xffffffffu, slt, o);
        sti += __shfl_xor_sync(0xffffffffu, sti, o);
        stt += __shfl_xor_sync(0xffffffffu, stt, o);
    }
    if ((tid & 31) == 0) {
        r0[tid >> 5] = sli; r1[tid >> 5] = slt;
        r2[tid >> 5] = sti; r3[tid >> 5] = stt;
    }
    __syncthreads();
    if (tid == 0) {
        float a = 0.f, b = 0.f, c = 0.f, d = 0.f;
#pragma unroll
        for (int w = 0; w < 8; w++) { a += r0[w]; b += r1[w]; c += r2[w]; d += r3[w]; }
        out[O_LOSS] = a / (float)BSZ + b / (float)BSZ;
        out[O_AVGI] = c / (float)BSZ;
        out[O_AVGT] = d / (float)BSZ;
    }
}

// =====================================================================
// ================  FALLBACK PATH (Round-6, proven)  ==================
// =====================================================================

__device__ __forceinline__ void mma_tf32(float* c, uint32_t a0, uint32_t a1,
                                         uint32_t a2, uint32_t a3,
                                         uint32_t b0, uint32_t b1) {
    asm volatile(
        "mma.sync.aligned.m16n8k8.row.col.f32.tf32.tf32.f32 "
        "{%0,%1,%2,%3}, {%4,%5,%6,%7}, {%8,%9}, {%0,%1,%2,%3};"
        : "+f"(c[0]), "+f"(c[1]), "+f"(c[2]), "+f"(c[3])
        : "r"(a0), "r"(a1), "r"(a2), "r"(a3), "r"(b0), "r"(b1));
}

struct SGemm { uint32_t As[4][128][20]; uint32_t Bs[4][128][20]; };
struct SEpi {
    float tauR[128], tauT[128];
    float pm[128][4], pS[128][4], pW[128][4];
    float cm[128][2], cS[128][2], cW[128][2];
};
union SUF { SGemm g; SEpi e; };

__global__ void __launch_bounds__(256) convert_pack(
    const float* __restrict__ A, const float* __restrict__ Bm)
{
    size_t idx = (size_t)blockIdx.x * 256 + threadIdx.x;
    const float* src;
    uint32_t* dst;
    if (idx < NCHUNK) { src = A; dst = g_A32; }
    else { idx -= NCHUNK; src = Bm; dst = g_B32; }

    const float4* s4 = (const float4*)src + idx * 4;
    float4 v0 = s4[0], v1 = s4[1], v2 = s4[2], v3 = s4[3];

    uint4 o0 = make_uint4(f2tf32(v0.x), f2tf32(v1.x), f2tf32(v0.y), f2tf32(v1.y));
    uint4 o1 = make_uint4(f2tf32(v0.z), f2tf32(v1.z), f2tf32(v0.w), f2tf32(v1.w));
    uint4 o2 = make_uint4(f2tf32(v2.x), f2tf32(v3.x), f2tf32(v2.y), f2tf32(v3.y));
    uint4 o3 = make_uint4(f2tf32(v2.z), f2tf32(v3.z), f2tf32(v2.w), f2tf32(v3.w));

    uint4* d4 = (uint4*)dst + idx * 4;
    d4[0] = o0; d4[1] = o1; d4[2] = o2; d4[3] = o3;
}

__global__ void __launch_bounds__(256, 2) gemm_fused(
    const float* __restrict__ tau_I, const float* __restrict__ tau_T,
    const int* __restrict__ image_ids, const int* __restrict__ text_ids,
    const float* __restrict__ s_I, const float* __restrict__ s_T,
    const float* __restrict__ u_I, const float* __restrict__ u_T,
    const float* __restrict__ b_I, const float* __restrict__ b_T,
    float* __restrict__ out)
{
    extern __shared__ __align__(16) char smbuf[];
    SUF& sm = *reinterpret_cast<SUF*>(smbuf);

    const int tid = threadIdx.x;

    if (blockIdx.x < NCOPY) {
        const float* srcs[8] = {s_I, s_T, u_I, u_T, b_I, b_T, tau_I, tau_T};
        const int gtid = blockIdx.x * 256 + tid;
        const int stride = NCOPY * 256;
#pragma unroll
        for (int a = 0; a < 8; a++) {
            const float4* src = (const float4*)srcs[a];
            float* dst = out + O_STATE + (size_t)a * NST;
            for (int i4 = gtid; i4 < NST / 4; i4 += stride) {
                float4 v = src[i4];
                float* d = dst + (size_t)i4 * 4;
                d[0] = v.x; d[1] = v.y; d[2] = v.z; d[3] = v.w;
            }
        }
        return;
    }

    const int bid = blockIdx.x - NCOPY;
    const int bx = bid & 31, by = bid >> 5;
    const int lane = tid & 31, wid = tid >> 5;
    const int m0 = by * 128, n0 = bx * 128;
    const int wm = (wid & 1) * 64, wn = (wid >> 1) * 32;
    const int g = lane >> 2, t4 = lane & 3;

    float acc[4][4][4];
#pragma unroll
    for (int a = 0; a < 4; a++)
#pragma unroll
        for (int b = 0; b < 4; b++)
#pragma unroll
            for (int r = 0; r < 4; r++) acc[a][b][r] = 0.f;

    auto load_stage = [&](int s, int k0, bool valid) {
        if (valid) {
#pragma unroll
            for (int it = 0; it < 2; it++) {
                int f = tid + it * 256;
                int r = f >> 2, kq = (f & 3) * 4;
                uint32_t da = (uint32_t)__cvta_generic_to_shared(&sm.g.As[s][r][kq]);
                const uint32_t* pa = g_A32 + (size_t)(m0 + r) * DIM + k0 + kq;
                asm volatile("cp.async.cg.shared.global [%0], [%1], 16;\n"
                             :: "r"(da), "l"(pa) : "memory");
                uint32_t db = (uint32_t)__cvta_generic_to_shared(&sm.g.Bs[s][r][kq]);
                const uint32_t* pb = g_B32 + (size_t)(n0 + r) * DIM + k0 + kq;
                asm volatile("cp.async.cg.shared.global [%0], [%1], 16;\n"
                             :: "r"(db), "l"(pb) : "memory");
            }
        }
        asm volatile("cp.async.commit_group;\n" ::: "memory");
    };

    auto compute_stage = [&](int s) {
#pragma unroll
        for (int ks = 0; ks < 2; ks++) {
            const int col = ks * 8 + 2 * t4;
            uint32_t af[4][4], bf[4][2];
#pragma unroll
            for (int mt = 0; mt < 4; mt++) {
                int mb = wm + mt * 16 + g;
                uint2 lo = *(const uint2*)&sm.g.As[s][mb][col];
                uint2 hi = *(const uint2*)&sm.g.As[s][mb + 8][col];
                af[mt][0] = lo.x; af[mt][2] = lo.y;
                af[mt][1] = hi.x; af[mt][3] = hi.y;
            }
#pragma unroll
            for (int nt = 0; nt < 4; nt++) {
                int nb = wn + nt * 8 + g;
                uint2 vb = *(const uint2*)&sm.g.Bs[s][nb][col];
                bf[nt][0] = vb.x; bf[nt][1] = vb.y;
            }
#pragma unroll
            for (int mt = 0; mt < 4; mt++)
#pragma unroll
                for (int nt = 0; nt < 4; nt++)
                    mma_tf32(acc[mt][nt], af[mt][0], af[mt][1], af[mt][2],
                             af[mt][3], bf[nt][0], bf[nt][1]);
        }
    };

    load_stage(0, 0, true);
    load_stage(1, 16, true);
    load_stage(2, 32, true);
#pragma unroll 1
    for (int kt = 0; kt < 64; kt++) {
        asm volatile("cp.async.wait_group 2;\n" ::: "memory");
        __syncthreads();
        int nx = kt + 3;
        load_stage(nx & 3, nx * 16, nx < 64);
        compute_stage(kt & 3);
    }
    __syncthreads();

    if (bx == by) {
#pragma unroll
        for (int mt = 0; mt < 4; mt++)
#pragma unroll
            for (int nt = 0; nt < 4; nt++)
#pragma unroll
                for (int h = 0; h < 2; h++)
#pragma unroll
                    for (int ci = 0; ci < 2; ci++) {
                        int rl = wm + mt * 16 + g + 8 * h;
                        int cl = wn + nt * 8 + t4 * 2 + ci;
                        if (rl == cl) g_diag[m0 + rl] = acc[mt][nt][2 * h + ci];
                    }
    }

    if (tid < 128) sm.e.tauR[tid] = tau_I[image_ids[m0 + tid]];
    else           sm.e.tauT[tid - 128] = tau_T[text_ids[n0 + tid - 128]];
    __syncthreads();

#pragma unroll
    for (int mt = 0; mt < 4; mt++) {
#pragma unroll
        for (int h = 0; h < 2; h++) {
            int rl = wm + mt * 16 + g + 8 * h;
            float inv = 1.0f / sm.e.tauR[rl];
            float y[8];
#pragma unroll
            for (int nt = 0; nt < 4; nt++) {
                y[nt * 2]     = acc[mt][nt][2 * h] * inv;
                y[nt * 2 + 1] = acc[mt][nt][2 * h + 1] * inv;
            }
            float m = y[0];
#pragma unroll
            for (int q = 1; q < 8; q++) m = fmaxf(m, y[q]);
            float S = 0.f, W = 0.f;
#pragma unroll
            for (int q = 0; q < 8; q++) {
                float e = __expf(y[q] - m);
                S += e; W += e * y[q];
            }
#pragma unroll
            for (int o = 1; o <= 2; o <<= 1) {
                float om = __shfl_xor_sync(0xffffffffu, m, o);
                float oS = __shfl_xor_sync(0xffffffffu, S, o);
                float oW = __shfl_xor_sync(0xffffffffu, W, o);
                omerge(m, S, W, om, oS, oW);
            }
            if (t4 == 0) {
                sm.e.pm[rl][wid >> 1] = m;
                sm.e.pS[rl][wid >> 1] = S;
                sm.e.pW[rl][wid >> 1] = W;
            }
        }
    }

#pragma unroll
    for (int nt = 0; nt < 4; nt++) {
#pragma unroll
        for (int ci = 0; ci < 2; ci++) {
            int cl = wn + nt * 8 + t4 * 2 + ci;
            float inv = 1.0f / sm.e.tauT[cl];
            float y[8];
#pragma unroll
            for (int mt = 0; mt < 4; mt++) {
                y[mt * 2]     = acc[mt][nt][ci] * inv;
                y[mt * 2 + 1] = acc[mt][nt][2 + ci] * inv;
            }
            float m = y[0];
#pragma unroll
            for (int q = 1; q < 8; q++) m = fmaxf(m, y[q]);
            float S = 0.f, W = 0.f;
#pragma unroll
            for (int q = 0; q < 8; q++) {
                float e = __expf(y[q] - m);
                S += e; W += e * y[q];
            }
#pragma unroll
            for (int o = 4; o <= 16; o <<= 1) {
                float om = __shfl_xor_sync(0xffffffffu, m, o);
                float oS = __shfl_xor_sync(0xffffffffu, S, o);
                float oW = __shfl_xor_sync(0xffffffffu, W, o);
                omerge(m, S, W, om, oS, oW);
            }
            if (g == 0) {
                sm.e.cm[cl][wid & 1] = m;
                sm.e.cS[cl][wid & 1] = S;
                sm.e.cW[cl][wid & 1] = W;
            }
        }
    }
    __syncthreads();

    if (tid < 128) {
        float m = sm.e.pm[tid][0], S = sm.e.pS[tid][0], W = sm.e.pW[tid][0];
#pragma unroll
        for (int p = 1; p < 4; p++)
            omerge(m, S, W, sm.e.pm[tid][p], sm.e.pS[tid][p], sm.e.pW[tid][p]);
        size_t o = (size_t)(m0 + tid) * 32 + bx;
        g_rowM[o] = m; g_rowS[o] = S; g_rowW[o] = W;

        float m2 = sm.e.cm[tid][0], S2 = sm.e.cS[tid][0], W2 = sm.e.cW[tid][0];
        omerge(m2, S2, W2, sm.e.cm[tid][1], sm.e.cS[tid][1], sm.e.cW[tid][1]);
        size_t o2 = (size_t)(n0 + tid) * 32 + by;
        g_colM[o2] = m2; g_colS[o2] = S2; g_colW[o2] = W2;
    }
}

__global__ void __launch_bounds__(256) merge_fb(
    const float* __restrict__ tau_I, const float* __restrict__ s_I,
    const float* __restrict__ u_I, const float* __restrict__ b_I,
    const float* __restrict__ tau_T, const float* __restrict__ s_T,
    const float* __restrict__ u_T, const float* __restrict__ b_T,
    const int* __restrict__ image_ids, const int* __restrict__ text_ids,
    const int* __restrict__ epoch, const int* __restrict__ max_epoch,
    float* __restrict__ out)
{
    const bool is_col = blockIdx.x >= (BSZ / 8);
    const int base = is_col ? blockIdx.x - BSZ / 8 : blockIdx.x;
    const int i = base * 8 + (threadIdx.x >> 5);
    const int lane = threadIdx.x & 31;

    const float* gM = is_col ? g_colM : g_rowM;
    const float* gS = is_col ? g_colS : g_rowS;
    const float* gW = is_col ? g_colW : g_rowW;
    const int* ids = is_col ? text_ids : image_ids;
    const float* tauA = is_col ? tau_T : tau_I;
    const float* sA = is_col ? s_T : s_I;
    const float* uA = is_col ? u_T : u_I;
    const float* bA = is_col ? b_T : b_I;

    float m = gM[i * 32 + lane];
    float S = gS[i * 32 + lane];
    float W = gW[i * 32 + lane];
    float M = m;
#pragma unroll
    for (int o = 16; o; o >>= 1) M = fmaxf(M, __shfl_xor_sync(0xffffffffu, M, o));
    const int id = ids[i];
    const float tau = tauA[id];
    const float d = g_diag[i] / tau;
    const float old_b = bA[id];
    const float new_b = fmaxf(M - d, old_b);
    float e = __expf(m - d - new_b);
    float Sx = S * e;
    float Wx = (W - d * S) * e;
#pragma unroll
    for (int o = 16; o; o >>= 1) {
        Sx += __shfl_xor_sync(0xffffffffu, Sx, o);
        Wx += __shfl_xor_sync(0xffffffffu, Wx, o);
    }
    if (lane == 0) {
        const float gv = Sx / (float)(BSZ - 1);
        const float s_new = (1.f - GAMMA_S) * sA[id] * expf(old_b - new_b) + GAMMA_S * gv;
        const float wsum = Wx / (s_new + EPS_) / (float)(BSZ - 1);
        const float loss = tau * wsum;
        const float grad = logf(s_new) + new_b + RHO - wsum;
        const float gclip = fminf(fmaxf(grad, -GRAD_CLIP_), GRAD_CLIP_);
        const float u_new = (1.f - GAMMA_U) * uA[id] + GAMMA_U * gclip;
        const float eta = eta_of(*epoch, *max_epoch);
        const float tau_new = fminf(fmaxf(tau - eta * u_new, TAU_MIN_), TAU_MAX_);
        if (!is_col) {
            out[OG_I + i] = gv;   out[OGR_I + i] = grad;
            g_loss_img[i] = loss; g_tau_img[i] = tau;
            out[O_SI + id] = s_new;  out[O_BI + id] = new_b;
            out[O_UI + id] = u_new;  out[O_TAUI + id] = tau_new;
        } else {
            out[OG_T + i] = gv;   out[OGR_T + i] = grad;
            g_loss_txt[i] = loss; g_tau_txt[i] = tau;
            out[O_ST + id] = s_new;  out[O_BT + id] = new_b;
            out[O_UT + id] = u_new;  out[O_TAUT + id] = tau_new;
        }
    }
}

// ===================== launch =====================

typedef CUresult (*PFN_tmap)(CUtensorMap*, CUtensorMapDataType, cuuint32_t, void*,
                             const cuuint64_t*, const cuuint64_t*, const cuuint32_t*,
                             const cuuint32_t*, CUtensorMapInterleave, CUtensorMapSwizzle,
                             CUtensorMapL2promotion, CUtensorMapFloatOOBfill);

extern "C" void kernel_launch(void* const* d_in, const int* in_sizes, int n_in,
                              void* d_out, int out_size)
{
    const float* imf   = (const float*)d_in[0];
    const float* txf   = (const float*)d_in[1];
    const float* s_I   = (const float*)d_in[2];
    const float* s_T   = (const float*)d_in[3];
    const float* tau_I = (const float*)d_in[4];
    const float* tau_T = (const float*)d_in[5];
    const float* u_I   = (const float*)d_in[6];
    const float* u_T   = (const float*)d_in[7];
    const float* b_I   = (const float*)d_in[8];
    const float* b_T   = (const float*)d_in[9];
    const int* image_ids = (const int*)d_in[10];
    const int* text_ids  = (const int*)d_in[11];
    const int* epoch     = (const int*)d_in[12];
    const int* max_epoch = (const int*)d_in[13];
    float* out = (float*)d_out;

    static CUtensorMap tmA, tmB;
    static int use_tc = -1;
    if (use_tc < 0) {
        cudaFuncSetAttribute(gemm_fused, cudaFuncAttributeMaxDynamicSharedMemorySize,
                             (int)sizeof(SUF));
        cudaFuncSetAttribute(gemm_tc, cudaFuncAttributeMaxDynamicSharedMemorySize, SMEM_TC);
        int v = 0;
        cudaMemcpyFromSymbol(&v, g_use_tc, sizeof(int));
        if (v) {
            void* fp = nullptr;
            cudaDriverEntryPointQueryResult qr;
            cudaGetDriverEntryPoint("cuTensorMapEncodeTiled", &fp, cudaEnableDefault, &qr);
            PFN_tmap enc = (PFN_tmap)fp;
            if (!enc) v = 0;
            else {
                void *pA, *pB;
                cudaGetSymbolAddress(&pA, g_A32);
                cudaGetSymbolAddress(&pB, g_B32);
                cuuint64_t dims[2] = {DIM, BSZ};
                cuuint64_t strides[1] = {DIM * 4};
                cuuint32_t boxA[2] = {32, 128}, boxB[2] = {32, 128}, es[2] = {1, 1};
                CUresult r1 = enc(&tmA, CU_TENSOR_MAP_DATA_TYPE_FLOAT32, 2, pA, dims, strides,
                                  boxA, es, CU_TENSOR_MAP_INTERLEAVE_NONE,
                                  CU_TENSOR_MAP_SWIZZLE_128B,
                                  CU_TENSOR_MAP_L2_PROMOTION_L2_128B,
                                  CU_TENSOR_MAP_FLOAT_OOB_FILL_NONE);
                CUresult r2 = enc(&tmB, CU_TENSOR_MAP_DATA_TYPE_FLOAT32, 2, pB, dims, strides,
                                  boxB, es, CU_TENSOR_MAP_INTERLEAVE_NONE,
                                  CU_TENSOR_MAP_SWIZZLE_128B,
                                  CU_TENSOR_MAP_L2_PROMOTION_L2_128B,
                                  CU_TENSOR_MAP_FLOAT_OOB_FILL_NONE);
                if (r1 != CUDA_SUCCESS || r2 != CUDA_SUCCESS) v = 0;
            }
        }
        use_tc = v;
    }

    if (use_tc) {
        convert_tf32<<<(2 * BSZ * DIM / 4) / 256, 256>>>(imf, txf);

        cudaLaunchConfig_t cfg = {};
        cfg.gridDim = dim3(NCPB + 512, 1, 1);   // 128 copy + 512 gemm (256 cg2 pairs)
        cfg.blockDim = dim3(128, 1, 1);
        cfg.dynamicSmemBytes = SMEM_TC;
        cudaLaunchAttribute attrs[1];
        attrs[0].id = cudaLaunchAttributeClusterDimension;
        attrs[0].val.clusterDim = {2, 1, 1};
        cfg.attrs = attrs;
        cfg.numAttrs = 1;
        cudaLaunchKernelEx(&cfg, gemm_tc, tmA, tmB, tau_I, tau_T,
                           image_ids, text_ids, s_I, s_T, u_I, u_T, b_I, b_T, out);

        merge_tc<<<2 * (BSZ / 8), 256>>>(tau_I, s_I, u_I, b_I,
                                         tau_T, s_T, u_T, b_T,
                                         image_ids, text_ids, epoch, max_epoch, out);
        finalize_tc<<<1, 256>>>(out);
    } else {
        convert_pack<<<2 * NCHUNK / 256, 256>>>(imf, txf);
        gemm_fused<<<NCOPY + 32 * 32, 256, sizeof(SUF)>>>(
            tau_I, tau_T, image_ids, text_ids,
            s_I, s_T, u_I, u_T, b_I, b_T, out);
        merge_fb<<<2 * (BSZ / 8), 256>>>(tau_I, s_I, u_I, b_I,
                                         tau_T, s_T, u_T, b_T,
                                         image_ids, text_ids, epoch, max_epoch, out);
        finalize_tc<<<1, 256>>>(out);
    }
}